// round 17
// baseline (speedup 1.0000x reference)
#include <cuda_runtime.h>
#include <cstdint>

#define N_PTS 65536
#define KNN   32
#define NKP   15
#define CIN   64
#define COUT  128
#define KDIM  (NKP * CIN)        // 960
#define INV_SIGMA 10.0f

#define SLICE   16384
#define NSLICE  (N_PTS / SLICE)  // 4

// ---------------- global scratch ---------------------------------------------
__device__ float g_weighted[(size_t)SLICE * KDIM];   // 63 MB, one slice
__device__ int   g_nb_is64;

// neighbors: int64 (reference dtype) or int32 (JAX default). Values < 65536 =>
// int64 means every odd 32-bit word is zero. Detect once.
__global__ void detect_idx_kernel(const int* __restrict__ nbw) {
    __shared__ int found;
    if (threadIdx.x == 0) found = 0;
    __syncthreads();
    int f = 0;
    for (int i = threadIdx.x; i < 65536; i += blockDim.x)
        if (nbw[2 * i + 1] != 0) f = 1;
    if (f) found = 1;
    __syncthreads();
    if (threadIdx.x == 0) g_nb_is64 = found ? 0 : 1;
}

__device__ __forceinline__ uint32_t tf32_rna(float x) {
    uint32_t y;
    asm("cvt.rna.tf32.f32 %0, %1;" : "=r"(y) : "f"(x));
    return y;
}

__device__ __forceinline__ void mma_tf32(float* d, uint32_t a0, uint32_t a1,
                                         uint32_t a2, uint32_t a3,
                                         uint32_t b0, uint32_t b1) {
    asm volatile(
        "mma.sync.aligned.m16n8k8.row.col.f32.tf32.tf32.f32 "
        "{%0,%1,%2,%3}, {%4,%5,%6,%7}, {%8,%9}, {%0,%1,%2,%3};\n"
        : "+f"(d[0]), "+f"(d[1]), "+f"(d[2]), "+f"(d[3])
        : "r"(a0), "r"(a1), "r"(a2), "r"(a3), "r"(b0), "r"(b1));
}

// ============================ Kernel A: gather (tensorized) ==================
// One point per warp: weighted[15,64] = infl[15,32] @ feats[nb,64] via
// m16n8k8 tf32 mma (m = Kp padded to 16, n = Cin, k = neighbors).
#define AS 36                       // A_s stride: 4*laneg+lane4 -> 32 banks
#define FS 72                       // F_s stride: 8*lane4+laneg -> 32 banks
#define WARP_WORDS (16 * AS + KNN * FS)          // 576 + 2304 = 2880
#define GA_SMEM_BYTES (8 * WARP_WORDS * 4)       // 92160 B -> 2 CTAs/SM

__global__ __launch_bounds__(256)
void kpconv_gather_kernel(const float* __restrict__ pos,
                          const float* __restrict__ feats,
                          const float* __restrict__ kpts,
                          const int*   __restrict__ nbw,
                          int n0)
{
    extern __shared__ float sm_g[];
    __shared__ float kp_s[48];

    const int tid  = threadIdx.x;
    const int lane = tid & 31;
    const int warp = tid >> 5;
    const int n    = n0 + blockIdx.x * 8 + warp;   // one point per warp
    const int scale = 1 + g_nb_is64;

    float* A_s = sm_g + warp * WARP_WORDS;         // [16 q][AS]
    float* F_s = A_s + 16 * AS;                    // [32 k][FS]

    if (tid < NKP * 3) kp_s[tid] = kpts[tid];
    __syncthreads();

    // ---- lane = neighbor k: influences -> A_s[q][k] (tf32) ----
    int nbi = nbw[(n * KNN + lane) * scale];
    float px = pos[3 * n],   py = pos[3 * n + 1],   pz = pos[3 * n + 2];
    float rx = pos[3 * nbi]     - px;
    float ry = pos[3 * nbi + 1] - py;
    float rz = pos[3 * nbi + 2] - pz;
    #pragma unroll
    for (int q = 0; q < NKP; q++) {
        float dx = rx - kp_s[3 * q];
        float dy = ry - kp_s[3 * q + 1];
        float dz = rz - kp_s[3 * q + 2];
        float dist = sqrtf(fmaf(dx, dx, fmaf(dy, dy, dz * dz)));
        float v = fmaxf(0.0f, fmaf(-dist, INV_SIGMA, 1.0f));
        *(uint32_t*)&A_s[q * AS + lane] = tf32_rna(v);
    }
    // zero padded row q=15 (keeps D row 15 finite; it is never stored)
    *(uint32_t*)&A_s[15 * AS + lane] = 0u;

    // ---- gather feats rows -> F_s[k][ch] (tf32) ----
    #pragma unroll
    for (int k = 0; k < KNN; k++) {
        int nk = __shfl_sync(0xffffffffu, nbi, k);
        float2 f = *(const float2*)&feats[nk * CIN + 2 * lane];
        uint2 v = make_uint2(tf32_rna(f.x), tf32_rna(f.y));
        *(uint2*)&F_s[k * FS + 2 * lane] = v;
    }
    __syncwarp();

    // ---- 32x m16n8k8: D[16 q][64 ch] ----
    const int lane4 = lane & 3;
    const int laneg = lane >> 2;

    float c[8][4];
    #pragma unroll
    for (int nb = 0; nb < 8; nb++)
        #pragma unroll
        for (int i = 0; i < 4; i++) c[nb][i] = 0.f;

    #pragma unroll
    for (int k8 = 0; k8 < 4; k8++) {
        const float* Ab = A_s + laneg * AS + k8 * 8 + lane4;
        uint32_t a0 = __float_as_uint(Ab[0]);
        uint32_t a1 = __float_as_uint(Ab[8 * AS]);
        uint32_t a2 = __float_as_uint(Ab[4]);
        uint32_t a3 = __float_as_uint(Ab[8 * AS + 4]);
        const float* Bb = F_s + (k8 * 8 + lane4) * FS + laneg;
        #pragma unroll
        for (int nb = 0; nb < 8; nb++) {
            uint32_t b0 = __float_as_uint(Bb[nb * 8]);
            uint32_t b1 = __float_as_uint(Bb[nb * 8 + 4 * FS]);
            mma_tf32(c[nb], a0, a1, a2, a3, b0, b1);
        }
    }

    // ---- store: weighted[n-n0][q*64+ch], rows q = laneg and laneg+8 ----
    float* grow = g_weighted + (size_t)(n - n0) * KDIM;
    #pragma unroll
    for (int nb = 0; nb < 8; nb++) {
        int col = nb * 8 + 2 * lane4;
        *(uint2*)&grow[laneg * CIN + col] =
            make_uint2(tf32_rna(c[nb][0]), tf32_rna(c[nb][1]));
        if (laneg < 7)
            *(uint2*)&grow[(laneg + 8) * CIN + col] =
                make_uint2(tf32_rna(c[nb][2]), tf32_rna(c[nb][3]));
    }
}

// ============================ Kernel B: GEMM (R15, mma.sync) =================
// out[n0:n0+SLICE,128] = g_weighted[0:SLICE,960] @ W[960,128] (tf32 mma)
#define ASTRIDE 36     // 36 % 32 == 4 -> conflict-free A frag loads
#define BSTR    136    // 136 % 32 == 8 -> conflict-free B frag loads
#define SZ_A    (128 * ASTRIDE)
#define SZ_B    (32 * BSTR)
#define GB_SMEM_WORDS (2 * SZ_A + 2 * SZ_B)
#define GB_SMEM_BYTES (GB_SMEM_WORDS * 4)   // 71680 B
#define NCHUNK  (KDIM / 32)            // 30

__device__ __forceinline__ void cp16(float* dst_s, const float* src_g) {
    uint32_t d;
    asm("{ .reg .u64 t; cvta.to.shared.u64 t, %1; cvt.u32.u64 %0, t; }"
        : "=r"(d) : "l"(dst_s));
    asm volatile("cp.async.cg.shared.global [%0], [%1], 16;\n"
                 :: "r"(d), "l"(src_g));
}

__device__ __forceinline__ void load_chunk(float* a_s, float* w_s,
                                           const float* __restrict__ Wg,
                                           int mrow, int c, int tid) {
    const float* Ag = g_weighted;
    int kc = c * 32;
    #pragma unroll
    for (int i = 0; i < 4; i++) {
        int e = i * 256 + tid;
        int row = e >> 3;
        int seg = e & 7;
        cp16(a_s + row * ASTRIDE + seg * 4,
             Ag + (size_t)(mrow + row) * KDIM + kc + seg * 4);
    }
    #pragma unroll
    for (int i = 0; i < 4; i++) {
        int e = i * 256 + tid;
        int row = e >> 5;
        int seg = e & 31;
        cp16(w_s + row * BSTR + seg * 4,
             Wg + (size_t)(kc + row) * COUT + seg * 4);
    }
    asm volatile("cp.async.commit_group;\n");
}

__global__ __launch_bounds__(256)
void kpconv_gemm_kernel(const float* __restrict__ Wg,
                        float*       __restrict__ out,
                        int n0)
{
    extern __shared__ float sm[];
    float* a_buf[2] = { sm, sm + SZ_A };
    float* w_buf[2] = { sm + 2 * SZ_A, sm + 2 * SZ_A + SZ_B };

    const int tid  = threadIdx.x;
    const int lane = tid & 31;
    const int warp = tid >> 5;
    const int mrow = blockIdx.x * 128;
    const int m0   = n0 + mrow;

    const int warp_m = warp >> 2;
    const int warp_n = warp & 3;
    const int lane4  = lane & 3;
    const int laneg  = lane >> 2;

    load_chunk(a_buf[0], w_buf[0], Wg, mrow, 0, tid);
    load_chunk(a_buf[1], w_buf[1], Wg, mrow, 1, tid);

    float acc[4][4][4];
    #pragma unroll
    for (int mf = 0; mf < 4; mf++)
        #pragma unroll
        for (int nf = 0; nf < 4; nf++)
            #pragma unroll
            for (int i = 0; i < 4; i++) acc[mf][nf][i] = 0.f;

    for (int c = 0; c < NCHUNK; c++) {
        if (c == NCHUNK - 1) { asm volatile("cp.async.wait_group 0;\n"); }
        else                 { asm volatile("cp.async.wait_group 1;\n"); }
        __syncthreads();
        const float* As = a_buf[c & 1];
        const float* Ws = w_buf[c & 1];

        #pragma unroll
        for (int k8 = 0; k8 < 4; k8++) {
            uint32_t af[4][4];
            #pragma unroll
            for (int mf = 0; mf < 4; mf++) {
                const float* A = As + (warp_m * 64 + mf * 16 + laneg) * ASTRIDE
                                    + k8 * 8 + lane4;
                af[mf][0] = __float_as_uint(A[0]);
                af[mf][1] = __float_as_uint(A[8 * ASTRIDE]);
                af[mf][2] = __float_as_uint(A[4]);
                af[mf][3] = __float_as_uint(A[8 * ASTRIDE + 4]);
            }
            uint32_t bf[4][2];
            #pragma unroll
            for (int nf = 0; nf < 4; nf++) {
                const float* B = Ws + (k8 * 8 + lane4) * BSTR
                                    + warp_n * 32 + nf * 8 + laneg;
                bf[nf][0] = __float_as_uint(B[0]);
                bf[nf][1] = __float_as_uint(B[4 * BSTR]);
            }
            #pragma unroll
            for (int mf = 0; mf < 4; mf++)
                #pragma unroll
                for (int nf = 0; nf < 4; nf++)
                    mma_tf32(acc[mf][nf], af[mf][0], af[mf][1], af[mf][2],
                             af[mf][3], bf[nf][0], bf[nf][1]);
        }
        __syncthreads();
        if (c + 2 < NCHUNK) load_chunk(a_buf[c & 1], w_buf[c & 1], Wg, mrow, c + 2, tid);
    }

    #pragma unroll
    for (int mf = 0; mf < 4; mf++) {
        int r = m0 + warp_m * 64 + mf * 16 + laneg;
        #pragma unroll
        for (int nf = 0; nf < 4; nf++) {
            int col = warp_n * 32 + nf * 8 + lane4 * 2;
            *(float2*)&out[(size_t)r * COUT + col] =
                make_float2(acc[mf][nf][0], acc[mf][nf][1]);
            *(float2*)&out[(size_t)(r + 8) * COUT + col] =
                make_float2(acc[mf][nf][2], acc[mf][nf][3]);
        }
    }
}

// ============================ launcher =======================================
extern "C" void kernel_launch(void* const* d_in, const int* in_sizes, int n_in,
                              void* d_out, int out_size)
{
    const float* pos   = (const float*)d_in[0];
    const float* feats = (const float*)d_in[1];
    const float* kpts  = (const float*)d_in[2];
    const float* Wg    = (const float*)d_in[3];
    const int*   nbw   = (const int*)d_in[4];
    float* out = (float*)d_out;

    cudaFuncSetAttribute(kpconv_gather_kernel,
                         cudaFuncAttributeMaxDynamicSharedMemorySize, GA_SMEM_BYTES);
    cudaFuncSetAttribute(kpconv_gemm_kernel,
                         cudaFuncAttributeMaxDynamicSharedMemorySize, GB_SMEM_BYTES);

    detect_idx_kernel<<<1, 256>>>(nbw);
    for (int s = 0; s < NSLICE; s++) {
        kpconv_gather_kernel<<<SLICE / 8, 256, GA_SMEM_BYTES>>>(pos, feats, kpts, nbw, s * SLICE);
        kpconv_gemm_kernel<<<SLICE / 128, 256, GB_SMEM_BYTES>>>(Wg, out, s * SLICE);
    }
}